// round 1
// baseline (speedup 1.0000x reference)
#include <cuda_runtime.h>

#define FULLMASK 0xffffffffu

constexpr int NB = 64;        // number of 64-row blocks (S=4096)
constexpr int BLK = 64;       // block size
constexpr int DIM = 128;      // head dim
constexpr int NSPLIT = 8;     // key-block splits
constexpr int JPER = NB / NSPLIT;
constexpr int NTHREADS = 256;
constexpr int SC_STR = 65;    // padded score-tile stride
constexpr int SEQ = NB * BLK; // 4096

// split partials: 8 * 4096 * 128 floats = 16 MB (static device scratch — no allocs)
__device__ float g_partial[NSPLIT * SEQ * DIM];

__device__ __forceinline__ float warp_sum(float v) {
#pragma unroll
  for (int o = 16; o; o >>= 1) v += __shfl_xor_sync(FULLMASK, v, o);
  return v;
}
__device__ __forceinline__ float warp_max(float v) {
#pragma unroll
  for (int o = 16; o; o >>= 1) v = fmaxf(v, __shfl_xor_sync(FULLMASK, v, o));
  return v;
}

// Descending bitonic sort of 64 values held warp-wide:
// lane holds v0 (element index = lane) and v1 (element index = lane + 32).
__device__ __forceinline__ void bitonic64_desc(float& v0, float& v1, int lane) {
#pragma unroll
  for (int size = 2; size <= 64; size <<= 1) {
#pragma unroll
    for (int stride = size >> 1; stride > 0; stride >>= 1) {
      if (stride == 32) {
        // only occurs at size==64; both halves descending: lower index keeps max
        float hi = fmaxf(v0, v1), lo = fminf(v0, v1);
        v0 = hi; v1 = lo;
      } else {
        bool lower = (lane & stride) == 0;
        bool d0 = ((lane) & size) == 0;        // descending sub-block?
        bool d1 = ((lane + 32) & size) == 0;
        float o0 = __shfl_xor_sync(FULLMASK, v0, stride);
        float o1 = __shfl_xor_sync(FULLMASK, v1, stride);
        v0 = (d0 == lower) ? fmaxf(v0, o0) : fminf(v0, o0);
        v1 = (d1 == lower) ? fmaxf(v1, o1) : fminf(v1, o1);
      }
    }
  }
}

__global__ void __launch_bounds__(NTHREADS, 2)
eco_attn_kernel(const float* __restrict__ q, const float* __restrict__ k,
                const float* __restrict__ v) {
  extern __shared__ float smem[];
  float4* qs4 = (float4*)smem;                      // 64x128 fp32, swizzled, 32KB
  float4* ks4 = (float4*)(smem + BLK * DIM);        // 64x128 fp32, swizzled, 32KB
  float* sc  = smem + 2 * BLK * DIM;                // 64x65 score/prob tile
  int* ksm   = (int*)(sc + BLK * SC_STR);           // per-row K

  const int split = blockIdx.x;
  const int ib = blockIdx.y;
  const int tid = threadIdx.x;
  const int lane = tid & 31;
  const int wid = tid >> 5;
  const int ty = tid >> 4;      // 0..15 (score-tile row group / out row group)
  const int tx = tid & 15;      // 0..15 (score-tile col group / out col group)
  const int qsw = ty & 7;       // swizzle key, constant per thread
  const int ksw = tx & 7;

  // ---- load Q block once (coalesced global read, XOR-swizzled smem store) ----
  {
    const float4* qg = (const float4*)(q + (size_t)ib * BLK * DIM);
#pragma unroll
    for (int it = 0; it < (BLK * DIM / 4) / NTHREADS; it++) {
      int g = tid + it * NTHREADS;
      int c = g >> 5, d4 = g & 31;
      qs4[(c << 5) | (d4 ^ (c & 7))] = qg[g];
    }
  }

  float acc[4][8];
#pragma unroll
  for (int a = 0; a < 4; a++)
#pragma unroll
    for (int b = 0; b < 8; b++) acc[a][b] = 0.f;

  for (int jj = 0; jj < JPER; jj++) {
    const int jb = split * JPER + jj;

    // ---- load K block (swizzled). Safe vs concurrent prior-iter PV (disjoint arrays).
    {
      const float4* kg = (const float4*)(k + (size_t)jb * BLK * DIM);
#pragma unroll
      for (int it = 0; it < (BLK * DIM / 4) / NTHREADS; it++) {
        int g = tid + it * NTHREADS;
        int c = g >> 5, d4 = g & 31;
        ks4[(c << 5) | (d4 ^ (c & 7))] = kg[g];
      }
    }
    __syncthreads();  // K ready; prior-iter PV done (sc may now be overwritten)

    // ---- scores: 4x4 register tile per thread, rows ty+16rr, cols tx+16cc ----
    float sacc[4][4];
#pragma unroll
    for (int a = 0; a < 4; a++)
#pragma unroll
      for (int b = 0; b < 4; b++) sacc[a][b] = 0.f;

#pragma unroll 8
    for (int d4 = 0; d4 < 32; d4++) {
      float4 av[4], bv[4];
#pragma unroll
      for (int rr = 0; rr < 4; rr++)
        av[rr] = qs4[((ty + 16 * rr) << 5) | (d4 ^ qsw)];
#pragma unroll
      for (int cc = 0; cc < 4; cc++)
        bv[cc] = ks4[((tx + 16 * cc) << 5) | (d4 ^ ksw)];
#pragma unroll
      for (int rr = 0; rr < 4; rr++)
#pragma unroll
        for (int cc = 0; cc < 4; cc++) {
          float s = sacc[rr][cc];
          s = fmaf(av[rr].x, bv[cc].x, s);
          s = fmaf(av[rr].y, bv[cc].y, s);
          s = fmaf(av[rr].z, bv[cc].z, s);
          s = fmaf(av[rr].w, bv[cc].w, s);
          sacc[rr][cc] = s;
        }
    }
#pragma unroll
    for (int rr = 0; rr < 4; rr++)
#pragma unroll
      for (int cc = 0; cc < 4; cc++)
        sc[(ty + 16 * rr) * SC_STR + (tx + 16 * cc)] = sacc[rr][cc];
    __syncthreads();

    // ---- softmax + top-p prefix count (warp wid owns rows 8*wid..8*wid+7) ----
#pragma unroll 1
    for (int rr = 0; rr < 8; rr++) {
      const int r = (wid << 3) + rr;
      float* srow = sc + r * SC_STR;
      float x0 = srow[lane], x1 = srow[lane + 32];
      float m = warp_max(fmaxf(x0, x1));
      float e0 = __expf(x0 - m);
      float e1 = __expf(x1 - m);

      float v0 = e0, v1 = e1;
      bitonic64_desc(v0, v1, lane);

      // inclusive scan over sorted-descending values
      float c0 = v0;
#pragma unroll
      for (int o = 1; o < 32; o <<= 1) {
        float n = __shfl_up_sync(FULLMASK, c0, o);
        if (lane >= o) c0 += n;
      }
      float c1 = v1;
#pragma unroll
      for (int o = 1; o < 32; o <<= 1) {
        float n = __shfl_up_sync(FULLMASK, c1, o);
        if (lane >= o) c1 += n;
      }
      float tot0 = __shfl_sync(FULLMASK, c0, 31);
      c1 += tot0;
      float s = __shfl_sync(FULLMASK, c1, 31);
      float t = 0.95f * s;
      int K = __popc(__ballot_sync(FULLMASK, c0 < t)) +
              __popc(__ballot_sync(FULLMASK, c1 < t));

      // denominator = sum of e over FIRST K original columns (positional mask!)
      float den = warp_sum(((lane < K) ? e0 : 0.f) + ((lane + 32 < K) ? e1 : 0.f));
      float inv = 1.f / (den + 1e-8f);
      srow[lane]      = (lane < K)      ? e0 * inv : 0.f;
      srow[lane + 32] = (lane + 32 < K) ? e1 * inv : 0.f;
      if (lane == 0) ksm[r] = K;
    }
    __syncthreads();

    // ---- PV: acc[rows ty+16rr][cols 8tx..8tx+8] += probs @ V (V via L1) ----
    int kmax = ksm[ty];
    kmax = max(kmax, ksm[ty + 16]);
    kmax = max(kmax, ksm[ty + 32]);
    kmax = max(kmax, ksm[ty + 48]);
    const float4* vg = (const float4*)(v + (size_t)jb * BLK * DIM);
#pragma unroll 2
    for (int c = 0; c < kmax; c++) {
      float w0 = sc[(ty)*SC_STR + c];
      float w1 = sc[(ty + 16) * SC_STR + c];
      float w2 = sc[(ty + 32) * SC_STR + c];
      float w3 = sc[(ty + 48) * SC_STR + c];
      float4 va = __ldg(vg + c * 32 + (tx << 1));
      float4 vb = __ldg(vg + c * 32 + (tx << 1) + 1);
      acc[0][0] = fmaf(w0, va.x, acc[0][0]); acc[0][1] = fmaf(w0, va.y, acc[0][1]);
      acc[0][2] = fmaf(w0, va.z, acc[0][2]); acc[0][3] = fmaf(w0, va.w, acc[0][3]);
      acc[0][4] = fmaf(w0, vb.x, acc[0][4]); acc[0][5] = fmaf(w0, vb.y, acc[0][5]);
      acc[0][6] = fmaf(w0, vb.z, acc[0][6]); acc[0][7] = fmaf(w0, vb.w, acc[0][7]);
      acc[1][0] = fmaf(w1, va.x, acc[1][0]); acc[1][1] = fmaf(w1, va.y, acc[1][1]);
      acc[1][2] = fmaf(w1, va.z, acc[1][2]); acc[1][3] = fmaf(w1, va.w, acc[1][3]);
      acc[1][4] = fmaf(w1, vb.x, acc[1][4]); acc[1][5] = fmaf(w1, vb.y, acc[1][5]);
      acc[1][6] = fmaf(w1, vb.z, acc[1][6]); acc[1][7] = fmaf(w1, vb.w, acc[1][7]);
      acc[2][0] = fmaf(w2, va.x, acc[2][0]); acc[2][1] = fmaf(w2, va.y, acc[2][1]);
      acc[2][2] = fmaf(w2, va.z, acc[2][2]); acc[2][3] = fmaf(w2, va.w, acc[2][3]);
      acc[2][4] = fmaf(w2, vb.x, acc[2][4]); acc[2][5] = fmaf(w2, vb.y, acc[2][5]);
      acc[2][6] = fmaf(w2, vb.z, acc[2][6]); acc[2][7] = fmaf(w2, vb.w, acc[2][7]);
      acc[3][0] = fmaf(w3, va.x, acc[3][0]); acc[3][1] = fmaf(w3, va.y, acc[3][1]);
      acc[3][2] = fmaf(w3, va.z, acc[3][2]); acc[3][3] = fmaf(w3, va.w, acc[3][3]);
      acc[3][4] = fmaf(w3, vb.x, acc[3][4]); acc[3][5] = fmaf(w3, vb.y, acc[3][5]);
      acc[3][6] = fmaf(w3, vb.z, acc[3][6]); acc[3][7] = fmaf(w3, vb.w, acc[3][7]);
    }
    // no sync needed here: next iter's K-load touches only ks; sync follows it
  }

  // ---- write split partial ----
  float* pbase = g_partial + ((size_t)split * SEQ + (size_t)ib * BLK) * DIM;
#pragma unroll
  for (int rr = 0; rr < 4; rr++) {
    int r = ty + 16 * rr;
    float4* dst = (float4*)(pbase + r * DIM + (tx << 3));
    dst[0] = make_float4(acc[rr][0], acc[rr][1], acc[rr][2], acc[rr][3]);
    dst[1] = make_float4(acc[rr][4], acc[rr][5], acc[rr][6], acc[rr][7]);
  }
}

__global__ void reduce_partials(float* __restrict__ out) {
  const int idx = blockIdx.x * blockDim.x + threadIdx.x;  // over float4s
  const float4* p = (const float4*)g_partial;
  float4 s = p[idx];
#pragma unroll
  for (int sp = 1; sp < NSPLIT; sp++) {
    float4 t = p[(size_t)sp * (SEQ * DIM / 4) + idx];
    s.x += t.x; s.y += t.y; s.z += t.z; s.w += t.w;
  }
  ((float4*)out)[idx] = s;
}

extern "C" void kernel_launch(void* const* d_in, const int* in_sizes, int n_in,
                              void* d_out, int out_size) {
  const float* q = (const float*)d_in[0];
  const float* k = (const float*)d_in[1];
  const float* v = (const float*)d_in[2];
  float* out = (float*)d_out;

  const size_t smem_bytes =
      (size_t)(2 * BLK * DIM + BLK * SC_STR) * sizeof(float) + BLK * sizeof(int);
  cudaFuncSetAttribute(eco_attn_kernel, cudaFuncAttributeMaxDynamicSharedMemorySize,
                       (int)smem_bytes);

  dim3 grid(NSPLIT, NB);
  eco_attn_kernel<<<grid, NTHREADS, smem_bytes>>>(q, k, v);
  reduce_partials<<<(SEQ * DIM / 4) / 256, 256>>>(out);
}